// round 6
// baseline (speedup 1.0000x reference)
#include <cuda_runtime.h>
#include <cstdint>

// Beam hypotheses update — one block per batch row, scatter formulation.
// 512 threads/block; each thread owns one int4 column across all 9 slots:
// 9 front-batched int4 loads (MLP=9, addresses independent of meta), meta
// computed once per thread (9x fewer threads than per-slot grid), then 9
// convert+scatter float4 stores. No smem, no barriers.
// Output (f32, concat): len[B], worst[B], board[B,9], items[B,9,G].

#define NSLOT 9

__global__ __launch_bounds__(512) void beam_row_kernel(
    const int*   __restrict__ hyp,        // [B, hyp_w]
    const float* __restrict__ slp,        // [B]
    const int*   __restrict__ lnst,       // [B]
    const float* __restrict__ worst_in,   // [B]
    const float* __restrict__ board_in,   // [B, 9]
    const int*   __restrict__ items_in,   // [B, 9, G]  (G == 2048)
    const int*   __restrict__ curlen_ptr, // scalar (may be null)
    float*       __restrict__ out,
    int batch, int hyp_w)
{
    const int b   = blockIdx.x;
    const int tid = threadIdx.x;          // int4 column 0..511 (G/4 = 512)

    // ---- 9 front-batched source loads (addresses meta-independent) ----
    const int4* src_base = reinterpret_cast<const int4*>(
        items_in + (size_t)b * NSLOT * 2048);
    int4 a[NSLOT];
#pragma unroll
    for (int j = 0; j < NSLOT; j++)
        a[j] = __ldcs(&src_base[j * 512 + tid]);

    // ---- meta, once per thread ----
    const int cur_len   = curlen_ptr ? __ldg(curlen_ptr) : hyp_w;
    const int num_beams = NSLOT - 1;

    const float score = __ldg(&slp[b]) / (float)cur_len;   // length_penalty=1
    const int   ln    = __ldg(&lnst[b]);
    const float worst = __ldg(&worst_in[b]);
    const bool  cond  = (ln < num_beams) || (score > worst);
    const int   new_len = ln + 1;
    const int   ins_idx = (new_len > NSLOT) ? 0 : num_beams;

    float v[NSLOT], bin[NSLOT];
#pragma unroll
    for (int i = 0; i < NSLOT; i++) {
        bin[i] = __ldg(&board_in[(size_t)b * NSLOT + i]);
        v[i]   = (i == ins_idx) ? score : bin[i];
    }

    // dest[j] = rank of (v[j], j) under stable ascending order (if cond)
    int dest[NSLOT];
#pragma unroll
    for (int j = 0; j < NSLOT; j++) {
        int r = 0;
#pragma unroll
        for (int k = 0; k < NSLOT; k++)
            if (k != j)
                r += ((v[k] < v[j]) || (v[k] == v[j] && k < j)) ? 1 : 0;
        dest[j] = cond ? r : j;
    }

    // ---- scalar outputs ----
    if (tid == 0) {
        out[b]         = (float)(cond ? new_len : ln);
        // second smallest by (value, index)
        float m1 = v[0]; int m1i = 0;
#pragma unroll
        for (int i = 1; i < NSLOT; i++)
            if (v[i] < m1) { m1 = v[i]; m1i = i; }
        float m2 = 3.402823466e+38f;
#pragma unroll
        for (int i = 0; i < NSLOT; i++)
            if (i != m1i) m2 = fminf(m2, v[i]);
        const float new_worst =
            (new_len > num_beams) ? m2 : fminf(worst, score);
        out[batch + b] = cond ? new_worst : worst;

        float* ob = out + (size_t)2 * batch + (size_t)b * NSLOT;
#pragma unroll
        for (int j = 0; j < NSLOT; j++)
            ob[dest[j]] = cond ? v[j] : bin[j];
    }

    // ---- hyp overlay on the replaced slot (first cur_len elements) ----
    if (cond) {
        const int* h = hyp + (size_t)b * hyp_w;
        if ((cur_len & 3) == 0 && (hyp_w & 3) == 0) {
            if (tid < (cur_len >> 2)) {
                int4 hv = __ldg(&reinterpret_cast<const int4*>(h)[tid]);
#pragma unroll
                for (int j = 0; j < NSLOT; j++)
                    if (j == ins_idx) a[j] = hv;
            }
        } else {
            int base = tid << 2;
            if (base < cur_len) {
                int4 hv;
                hv.x = (base + 0 < cur_len) ? h[base + 0] : 0;
                hv.y = (base + 1 < cur_len) ? h[base + 1] : 0;
                hv.z = (base + 2 < cur_len) ? h[base + 2] : 0;
                hv.w = (base + 3 < cur_len) ? h[base + 3] : 0;
#pragma unroll
                for (int j = 0; j < NSLOT; j++)
                    if (j == ins_idx) {
                        if (base + 0 < cur_len) a[j].x = hv.x;
                        if (base + 1 < cur_len) a[j].y = hv.y;
                        if (base + 2 < cur_len) a[j].z = hv.z;
                        if (base + 3 < cur_len) a[j].w = hv.w;
                    }
            }
        }
    }

    // ---- 9 convert + scatter stores ----
    float4* dst_base = reinterpret_cast<float4*>(
        out + (size_t)batch * (2 + NSLOT) + (size_t)b * NSLOT * 2048);
#pragma unroll
    for (int j = 0; j < NSLOT; j++) {
        float4 f;
        f.x = (float)a[j].x; f.y = (float)a[j].y;
        f.z = (float)a[j].z; f.w = (float)a[j].w;
        __stcs(&dst_base[dest[j] * 512 + tid], f);
    }
}

// ---------------- generic fallback (arbitrary gen_len), per-slot grid ------
__global__ __launch_bounds__(128) void beam_scatter_kernel_gen(
    const int*   __restrict__ hyp,
    const float* __restrict__ slp,
    const int*   __restrict__ lnst,
    const float* __restrict__ worst_in,
    const float* __restrict__ board_in,
    const int*   __restrict__ items_in,
    const int*   __restrict__ curlen_ptr,
    float*       __restrict__ out,
    int batch, int hyp_w, int gen_len)
{
    const int j   = blockIdx.x;
    const int b   = blockIdx.y;
    const int tid = threadIdx.x;

    const int cur_len   = curlen_ptr ? __ldg(curlen_ptr) : hyp_w;
    const int num_beams = NSLOT - 1;

    const float score = __ldg(&slp[b]) / (float)cur_len;
    const int   ln    = __ldg(&lnst[b]);
    const float worst = __ldg(&worst_in[b]);
    const bool  cond  = (ln < num_beams) || (score > worst);
    const int   new_len = ln + 1;
    const int   ins_idx = (new_len > NSLOT) ? 0 : num_beams;

    float v[NSLOT];
    float binj = 0.f;
#pragma unroll
    for (int i = 0; i < NSLOT; i++) {
        v[i] = __ldg(&board_in[(size_t)b * NSLOT + i]);
        if (i == j) binj = v[i];
    }
#pragma unroll
    for (int i = 0; i < NSLOT; i++)
        if (i == ins_idx) v[i] = score;

    int r = 0;
#pragma unroll
    for (int k = 0; k < NSLOT; k++)
        if (k != j)
            r += ((v[k] < v[j]) || (v[k] == v[j] && k < j)) ? 1 : 0;

    const int  dest    = cond ? r : j;
    const bool use_hyp = cond && (j == ins_idx);

    if (tid == 0) {
        out[(size_t)2 * batch + (size_t)b * NSLOT + dest] = cond ? v[j] : binj;
        if (j == 0) {
            float m1 = v[0]; int m1i = 0;
#pragma unroll
            for (int i = 1; i < NSLOT; i++)
                if (v[i] < m1) { m1 = v[i]; m1i = i; }
            float m2 = 3.402823466e+38f;
#pragma unroll
            for (int i = 0; i < NSLOT; i++)
                if (i != m1i) m2 = fminf(m2, v[i]);
            const float new_worst =
                (new_len > num_beams) ? m2 : fminf(worst, score);
            out[b]         = (float)(cond ? new_len : ln);
            out[batch + b] = cond ? new_worst : worst;
        }
    }

    const int* src_row = items_in + ((size_t)b * NSLOT + j) * gen_len;
    float*     dst_row = out + (size_t)batch * (2 + NSLOT) +
                         ((size_t)b * NSLOT + dest) * gen_len;
    const int* h = hyp + (size_t)b * hyp_w;

    for (int e = tid; e < gen_len; e += 128) {
        int val = (use_hyp && e < cur_len) ? h[e] : __ldcs(&src_row[e]);
        __stcs(&dst_row[e], (float)val);
    }
}

extern "C" void kernel_launch(void* const* d_in, const int* in_sizes, int n_in,
                              void* d_out, int out_size)
{
    const int*   hyp    = (const int*)  d_in[0];
    const float* slp    = (const float*)d_in[1];
    const int*   lnst   = (const int*)  d_in[2];
    const float* worst  = (const float*)d_in[3];
    const float* board  = (const float*)d_in[4];
    const int*   items  = (const int*)  d_in[5];
    const int*   curlen = (n_in > 6) ? (const int*)d_in[6] : nullptr;

    const int batch   = in_sizes[1];
    const int hyp_w   = in_sizes[0] / batch;
    const int gen_len = in_sizes[5] / (batch * NSLOT);
    float* out = (float*)d_out;

    if (gen_len == 2048) {
        beam_row_kernel<<<batch, 512>>>(
            hyp, slp, lnst, worst, board, items, curlen, out,
            batch, hyp_w);
    } else {
        dim3 grid(NSLOT, batch);
        beam_scatter_kernel_gen<<<grid, 128>>>(
            hyp, slp, lnst, worst, board, items, curlen, out,
            batch, hyp_w, gen_len);
    }
}